// round 2
// baseline (speedup 1.0000x reference)
#include <cuda_runtime.h>
#include <math.h>

#define NCLS 40
#define QN 100
#define BN 4
#define HW 65536
#define THREADS 256
#define PPT 4
#define PIX (THREADS*PPT)          // 1024 pixels per block
#define NBLK (BN*HW/PIX)           // 256 blocks
#define NC1 (NCLS+1)

// ---- scratch (device globals; no allocation allowed) ----
__device__ float g_inter[BN*QN*NCLS];
__device__ float g_src[BN*QN];
__device__ int   g_counts[BN*QN*NCLS];
__device__ float g_ce_sum;
__device__ int   g_nvalid;

__global__ void zero_k() {
    int i = blockIdx.x * blockDim.x + threadIdx.x;
    if (i < BN*QN*NCLS) { g_inter[i] = 0.f; g_counts[i] = 0; }
    if (i < BN*QN) g_src[i] = 0.f;
    if (i == 0) { g_ce_sum = 0.f; g_nvalid = 0; }
}

// Main streaming pass over pred_masks.
// Block = 1024 contiguous pixels of one image; loop over q with coalesced loads.
// Per-pixel online state: sum(exp), max/argmax, value at q==target.
// inter[q][c] accumulated via class-sorted staging in shared memory.
__global__ __launch_bounds__(THREADS) void main_k(
    const float* __restrict__ masks, const int* __restrict__ targets)
{
    __shared__ float inter_sh[QN*NC1];          // 16.4 KB, class 40 = ignore bin
    __shared__ float sig_sh[2][PIX];            // double buffer: 1 barrier per q
    __shared__ unsigned char cls_sorted[PIX];
    __shared__ int s_cnt[NC1];
    __shared__ int s_base[NC1];
    __shared__ int s_cur[NC1];
    __shared__ float s_red[THREADS];

    const int tid = threadIdx.x;
    const int img = blockIdx.x / (HW/PIX);
    const int blk = blockIdx.x % (HW/PIX);
    const int pixbase = img*HW + blk*PIX;

    for (int i = tid; i < QN*NC1; i += THREADS) inter_sh[i] = 0.f;
    for (int i = tid; i < NC1; i += THREADS) s_cnt[i] = 0;
    __syncthreads();

    // ---- classes + counting sort of the block's pixels by class ----
    int myc[PPT], mypos[PPT];
    #pragma unroll
    for (int j = 0; j < PPT; j++) {
        int t = targets[pixbase + tid + THREADS*j];
        myc[j] = ((unsigned)t < (unsigned)NCLS) ? t : NCLS;   // 40 == ignore
        atomicAdd(&s_cnt[myc[j]], 1);
    }
    __syncthreads();
    if (tid == 0) {
        int r = 0;
        for (int c = 0; c < NC1; c++) { s_base[c] = r; r += s_cnt[c]; }
    }
    __syncthreads();
    for (int i = tid; i < NC1; i += THREADS) s_cur[i] = s_base[i];
    __syncthreads();
    #pragma unroll
    for (int j = 0; j < PPT; j++) {
        mypos[j] = atomicAdd(&s_cur[myc[j]], 1);
        cls_sorted[mypos[j]] = (unsigned char)myc[j];
    }
    __syncthreads();
    int accCls[PPT];
    #pragma unroll
    for (int j = 0; j < PPT; j++) accCls[j] = (int)cls_sorted[tid*PPT + j];

    float ssum[PPT], mmax[PPT], xt[PPT];
    int amax[PPT];
    #pragma unroll
    for (int j = 0; j < PPT; j++) { ssum[j] = 0.f; mmax[j] = -1e30f; xt[j] = 0.f; amax[j] = 0; }

    const float* base = masks + (size_t)img*QN*HW + (size_t)blk*PIX;

    for (int q = 0; q < QN; q++) {
        const float* row = base + (size_t)q*HW;
        float* sbuf = sig_sh[q & 1];
        #pragma unroll
        for (int j = 0; j < PPT; j++) {
            float x = __ldg(row + tid + THREADS*j);
            if (x > mmax[j]) { mmax[j] = x; amax[j] = q; }
            xt[j] = (q == myc[j]) ? x : xt[j];
            float xc = fminf(fmaxf(x, -15.f), 15.f);
            float t = __expf(xc);              // one exp serves both lse and sigmoid
            ssum[j] += t;
            float sg = __fdividef(t, 1.f + t); // sigmoid
            sbuf[mypos[j]] = sg;               // scatter to class-sorted slot
        }
        __syncthreads();
        // accumulate: 4 consecutive class-sorted slots -> mostly one run
        float4 v = reinterpret_cast<const float4*>(sbuf)[tid];
        float* ip = &inter_sh[q*NC1];
        float a = v.x; int c = accCls[0];
        if (accCls[1] == c) a += v.y; else { atomicAdd(ip + c, a); c = accCls[1]; a = v.y; }
        if (accCls[2] == c) a += v.z; else { atomicAdd(ip + c, a); c = accCls[2]; a = v.z; }
        if (accCls[3] == c) a += v.w; else { atomicAdd(ip + c, a); c = accCls[3]; a = v.w; }
        atomicAdd(ip + c, a);
        // no 2nd barrier: next q writes the other buffer; its barrier orders reuse
    }

    // ---- per-pixel epilogue: ce_mask numerator, n_valid, assignment counts ----
    float ce_l = 0.f, nv = 0.f;
    #pragma unroll
    for (int j = 0; j < PPT; j++) {
        if (myc[j] < NCLS) {
            ce_l += __logf(ssum[j]) - xt[j];   // lse - x[target]
            nv += 1.f;
            atomicAdd(&g_counts[(img*QN + amax[j])*NCLS + myc[j]], 1);
        }
    }
    __syncthreads();
    s_red[tid] = ce_l; __syncthreads();
    for (int s = THREADS/2; s > 0; s >>= 1) { if (tid < s) s_red[tid] += s_red[tid+s]; __syncthreads(); }
    if (tid == 0) atomicAdd(&g_ce_sum, s_red[0]);
    __syncthreads();
    s_red[tid] = nv; __syncthreads();
    for (int s = THREADS/2; s > 0; s >>= 1) { if (tid < s) s_red[tid] += s_red[tid+s]; __syncthreads(); }
    if (tid == 0) atomicAdd(&g_nvalid, (int)s_red[0]);
    __syncthreads();

    // ---- flush inter_sh -> global (src_sum = sum over all 41 bins incl. ignore) ----
    for (int q = tid; q < QN; q += THREADS) {
        float ss = 0.f;
        #pragma unroll 1
        for (int c = 0; c < NC1; c++) {
            float v = inter_sh[q*NC1 + c];
            ss += v;
            if (c < NCLS) atomicAdd(&g_inter[(img*QN + q)*NCLS + c], v);
        }
        atomicAdd(&g_src[img*QN + q], ss);
    }
}

// Final reduction: loss_ce (focal CE over 400 queries), dice, combine.
__global__ void fin_k(const float* __restrict__ logits, float* __restrict__ out)
{
    __shared__ float tsum_sh[BN*NCLS];
    __shared__ float pres_sh[NCLS];
    __shared__ float red[512];
    const int tid = threadIdx.x;

    for (int idx = tid; idx < BN*NCLS; idx += 512) {
        int b = idx / NCLS, c = idx % NCLS;
        int s = 0;
        for (int q = 0; q < QN; q++) s += g_counts[(b*QN + q)*NCLS + c];
        tsum_sh[idx] = (float)s;
    }
    __syncthreads();
    for (int c = tid; c < NCLS; c += 512) {
        float t = 0.f;
        for (int b = 0; b < BN; b++) t += tsum_sh[b*NCLS + c];
        pres_sh[c] = (t > 0.f) ? 1.f : 0.f;
    }
    __syncthreads();

    float ce_acc = 0.f, dice_acc = 0.f;
    for (int i = tid; i < BN*QN; i += 512) {
        int b = i / QN;
        // mode label = argmax of counts (ties -> smallest class); empty -> NCLS
        const int* cp = &g_counts[i*NCLS];
        int bestc = NCLS, bestcnt = 0;
        for (int c = 0; c < NCLS; c++) { int v = cp[c]; if (v > bestcnt) { bestcnt = v; bestc = c; } }
        if (bestc < NCLS) {
            const float* lg = logits + i*NC1;
            float m = -1e30f;
            for (int c = 0; c < NC1; c++) m = fmaxf(m, lg[c]);
            float s = 0.f;
            for (int c = 0; c < NC1; c++) s += __expf(lg[c] - m);
            float nll = m + __logf(s) - lg[bestc];     // weight = 1 for c < NCLS
            float p = __expf(-nll);
            float om = 1.f - p;
            ce_acc += om * om * nll;
        }
        float ss = g_src[i];
        for (int c = 0; c < NCLS; c++) {
            dice_acc += pres_sh[c] * 2.f * g_inter[i*NCLS + c]
                        / (ss + tsum_sh[b*NCLS + c] + 1e-8f);
        }
    }

    red[tid] = ce_acc; __syncthreads();
    for (int s = 256; s > 0; s >>= 1) { if (tid < s) red[tid] += red[tid+s]; __syncthreads(); }
    float ce_tot = red[0]; __syncthreads();
    red[tid] = dice_acc; __syncthreads();
    for (int s = 256; s > 0; s >>= 1) { if (tid < s) red[tid] += red[tid+s]; __syncthreads(); }
    float dice_tot = red[0]; __syncthreads();

    if (tid == 0) {
        float npres = 0.f;
        for (int c = 0; c < NCLS; c++) npres += pres_sh[c];
        float loss_ce = ce_tot / (float)(BN*QN);
        float ce_mask = g_ce_sum / fmaxf((float)g_nvalid, 1.f);
        float dice_loss = (npres - dice_tot / (float)(BN*QN)) / (float)NCLS;
        out[0] = 2.f*loss_ce + 5.f*ce_mask + 5.f*dice_loss;
    }
}

extern "C" void kernel_launch(void* const* d_in, const int* in_sizes, int n_in,
                              void* d_out, int out_size)
{
    const float* logits  = (const float*)d_in[0];   // [4,100,41] f32
    const float* masks   = (const float*)d_in[1];   // [4,100,256,256] f32
    const int*   targets = (const int*)d_in[2];     // [4,256,256] i32
    float* out = (float*)d_out;

    zero_k<<<(BN*QN*NCLS + 255)/256, 256>>>();
    main_k<<<NBLK, THREADS>>>(masks, targets);
    fin_k<<<1, 512>>>(logits, out);
}

// round 3
// speedup vs baseline: 1.3132x; 1.3132x over previous
#include <cuda_runtime.h>
#include <math.h>

#define NCLS 40
#define QN 100
#define BN 4
#define HW 65536
#define THREADS 256
#define PPT 4
#define PIX (THREADS*PPT)          // 1024 pixels per block
#define NBLK (BN*HW/PIX)           // 256 blocks
#define NC1 (NCLS+1)

// ---- scratch (device globals; no allocation allowed) ----
__device__ float g_inter[BN*QN*NCLS];
__device__ float g_src[BN*QN];
__device__ int   g_counts[BN*QN*NCLS];
__device__ float g_ce_sum;
__device__ int   g_nvalid;

__global__ void zero_k() {
    int i = blockIdx.x * blockDim.x + threadIdx.x;
    if (i < BN*QN*NCLS) { g_inter[i] = 0.f; g_counts[i] = 0; }
    if (i < BN*QN) g_src[i] = 0.f;
    if (i == 0) { g_ce_sum = 0.f; g_nvalid = 0; }
}

// Main streaming pass over pred_masks.
// Block = 1024 contiguous pixels of one image; loop over q, float4 per thread
// (4 contiguous pixels), register-prefetch of q+1 to hide DRAM latency.
// inter[q][c] accumulated via class-sorted staging in shared memory.
__global__ __launch_bounds__(THREADS) void main_k(
    const float* __restrict__ masks, const int* __restrict__ targets)
{
    __shared__ float inter_sh[QN*NC1];          // 16.4 KB, class 40 = ignore bin
    __shared__ float sig_sh[2][PIX];            // double buffer: 1 barrier per q
    __shared__ unsigned char cls_sorted[PIX];
    __shared__ int s_cnt[NC1];
    __shared__ int s_base[NC1];
    __shared__ int s_cur[NC1];
    __shared__ float s_red[THREADS];

    const int tid = threadIdx.x;
    const int img = blockIdx.x / (HW/PIX);
    const int blk = blockIdx.x % (HW/PIX);
    const int pixbase = img*HW + blk*PIX;

    for (int i = tid; i < QN*NC1; i += THREADS) inter_sh[i] = 0.f;
    for (int i = tid; i < NC1; i += THREADS) s_cnt[i] = 0;
    __syncthreads();

    // ---- classes (4 contiguous pixels/thread) + counting sort by class ----
    int myc[PPT], mypos[PPT];
    {
        int4 t4 = reinterpret_cast<const int4*>(targets + pixbase)[tid];
        int tt[PPT] = {t4.x, t4.y, t4.z, t4.w};
        #pragma unroll
        for (int j = 0; j < PPT; j++) {
            myc[j] = ((unsigned)tt[j] < (unsigned)NCLS) ? tt[j] : NCLS; // 40 == ignore
            atomicAdd(&s_cnt[myc[j]], 1);
        }
    }
    __syncthreads();
    if (tid == 0) {
        int r = 0;
        for (int c = 0; c < NC1; c++) { s_base[c] = r; r += s_cnt[c]; }
    }
    __syncthreads();
    for (int i = tid; i < NC1; i += THREADS) s_cur[i] = s_base[i];
    __syncthreads();
    #pragma unroll
    for (int j = 0; j < PPT; j++) {
        mypos[j] = atomicAdd(&s_cur[myc[j]], 1);
        cls_sorted[mypos[j]] = (unsigned char)myc[j];
    }
    __syncthreads();
    int accCls[PPT];
    #pragma unroll
    for (int j = 0; j < PPT; j++) accCls[j] = (int)cls_sorted[tid*PPT + j];

    float ssum[PPT], mmax[PPT], xt[PPT];
    int amax[PPT];
    #pragma unroll
    for (int j = 0; j < PPT; j++) { ssum[j] = 0.f; mmax[j] = -1e30f; xt[j] = 0.f; amax[j] = 0; }

    const float4* base4 = reinterpret_cast<const float4*>(
        masks + (size_t)img*QN*HW + (size_t)blk*PIX);
    const int stride4 = HW/4;

    float4 cur = base4[tid];                    // prefetch q=0
    for (int q = 0; q < QN; q++) {
        // prefetch q+1 before any dependent work / barrier
        float4 nxt;
        if (q + 1 < QN) nxt = base4[(size_t)(q+1)*stride4 + tid];
        else nxt = make_float4(0.f, 0.f, 0.f, 0.f);

        float xv[PPT] = {cur.x, cur.y, cur.z, cur.w};
        float* sbuf = sig_sh[q & 1];
        #pragma unroll
        for (int j = 0; j < PPT; j++) {
            float x = xv[j];
            if (x > mmax[j]) { mmax[j] = x; amax[j] = q; }
            xt[j] = (q == myc[j]) ? x : xt[j];
            float xc = fminf(fmaxf(x, -15.f), 15.f);
            float t = __expf(xc);              // one exp serves both lse and sigmoid
            ssum[j] += t;
            float sg = __fdividef(t, 1.f + t); // sigmoid
            sbuf[mypos[j]] = sg;               // scatter to class-sorted slot
        }
        __syncthreads();
        // accumulate: 4 consecutive class-sorted slots -> mostly one run
        float4 v = reinterpret_cast<const float4*>(sbuf)[tid];
        float* ip = &inter_sh[q*NC1];
        float a = v.x; int c = accCls[0];
        if (accCls[1] == c) a += v.y; else { atomicAdd(ip + c, a); c = accCls[1]; a = v.y; }
        if (accCls[2] == c) a += v.z; else { atomicAdd(ip + c, a); c = accCls[2]; a = v.z; }
        if (accCls[3] == c) a += v.w; else { atomicAdd(ip + c, a); c = accCls[3]; a = v.w; }
        atomicAdd(ip + c, a);
        cur = nxt;
        // no 2nd barrier: next q writes the other buffer; its barrier orders reuse
    }

    // ---- per-pixel epilogue: ce_mask numerator, n_valid, assignment counts ----
    float ce_l = 0.f, nv = 0.f;
    #pragma unroll
    for (int j = 0; j < PPT; j++) {
        if (myc[j] < NCLS) {
            ce_l += __logf(ssum[j]) - xt[j];   // lse - x[target]
            nv += 1.f;
            atomicAdd(&g_counts[(img*QN + amax[j])*NCLS + myc[j]], 1);
        }
    }
    __syncthreads();
    s_red[tid] = ce_l; __syncthreads();
    for (int s = THREADS/2; s > 0; s >>= 1) { if (tid < s) s_red[tid] += s_red[tid+s]; __syncthreads(); }
    if (tid == 0) atomicAdd(&g_ce_sum, s_red[0]);
    __syncthreads();
    s_red[tid] = nv; __syncthreads();
    for (int s = THREADS/2; s > 0; s >>= 1) { if (tid < s) s_red[tid] += s_red[tid+s]; __syncthreads(); }
    if (tid == 0) atomicAdd(&g_nvalid, (int)s_red[0]);
    __syncthreads();

    // ---- flush inter_sh -> global (src_sum = sum over all 41 bins incl. ignore) ----
    for (int q = tid; q < QN; q += THREADS) {
        float ss = 0.f;
        #pragma unroll 1
        for (int c = 0; c < NC1; c++) {
            float v = inter_sh[q*NC1 + c];
            ss += v;
            if (c < NCLS) atomicAdd(&g_inter[(img*QN + q)*NCLS + c], v);
        }
        atomicAdd(&g_src[img*QN + q], ss);
    }
}

// Final reduction: loss_ce (focal CE over 400 queries), dice, combine.
__global__ void fin_k(const float* __restrict__ logits, float* __restrict__ out)
{
    __shared__ float tsum_sh[BN*NCLS];
    __shared__ float pres_sh[NCLS];
    __shared__ float red[512];
    const int tid = threadIdx.x;

    for (int idx = tid; idx < BN*NCLS; idx += 512) {
        int b = idx / NCLS, c = idx % NCLS;
        int s = 0;
        for (int q = 0; q < QN; q++) s += g_counts[(b*QN + q)*NCLS + c];
        tsum_sh[idx] = (float)s;
    }
    __syncthreads();
    for (int c = tid; c < NCLS; c += 512) {
        float t = 0.f;
        for (int b = 0; b < BN; b++) t += tsum_sh[b*NCLS + c];
        pres_sh[c] = (t > 0.f) ? 1.f : 0.f;
    }
    __syncthreads();

    float ce_acc = 0.f, dice_acc = 0.f;
    for (int i = tid; i < BN*QN; i += 512) {
        int b = i / QN;
        // mode label = argmax of counts (ties -> smallest class); empty -> NCLS
        const int* cp = &g_counts[i*NCLS];
        int bestc = NCLS, bestcnt = 0;
        for (int c = 0; c < NCLS; c++) { int v = cp[c]; if (v > bestcnt) { bestcnt = v; bestc = c; } }
        if (bestc < NCLS) {
            const float* lg = logits + i*NC1;
            float m = -1e30f;
            for (int c = 0; c < NC1; c++) m = fmaxf(m, lg[c]);
            float s = 0.f;
            for (int c = 0; c < NC1; c++) s += __expf(lg[c] - m);
            float nll = m + __logf(s) - lg[bestc];     // weight = 1 for c < NCLS
            float p = __expf(-nll);
            float om = 1.f - p;
            ce_acc += om * om * nll;
        }
        float ss = g_src[i];
        for (int c = 0; c < NCLS; c++) {
            dice_acc += pres_sh[c] * 2.f * g_inter[i*NCLS + c]
                        / (ss + tsum_sh[b*NCLS + c] + 1e-8f);
        }
    }

    red[tid] = ce_acc; __syncthreads();
    for (int s = 256; s > 0; s >>= 1) { if (tid < s) red[tid] += red[tid+s]; __syncthreads(); }
    float ce_tot = red[0]; __syncthreads();
    red[tid] = dice_acc; __syncthreads();
    for (int s = 256; s > 0; s >>= 1) { if (tid < s) red[tid] += red[tid+s]; __syncthreads(); }
    float dice_tot = red[0]; __syncthreads();

    if (tid == 0) {
        float npres = 0.f;
        for (int c = 0; c < NCLS; c++) npres += pres_sh[c];
        float loss_ce = ce_tot / (float)(BN*QN);
        float ce_mask = g_ce_sum / fmaxf((float)g_nvalid, 1.f);
        float dice_loss = (npres - dice_tot / (float)(BN*QN)) / (float)NCLS;
        out[0] = 2.f*loss_ce + 5.f*ce_mask + 5.f*dice_loss;
    }
}

extern "C" void kernel_launch(void* const* d_in, const int* in_sizes, int n_in,
                              void* d_out, int out_size)
{
    const float* logits  = (const float*)d_in[0];   // [4,100,41] f32
    const float* masks   = (const float*)d_in[1];   // [4,100,256,256] f32
    const int*   targets = (const int*)d_in[2];     // [4,256,256] i32
    float* out = (float*)d_out;

    zero_k<<<(BN*QN*NCLS + 255)/256, 256>>>();
    main_k<<<NBLK, THREADS>>>(masks, targets);
    fin_k<<<1, 512>>>(logits, out);
}

// round 6
// speedup vs baseline: 1.9459x; 1.4819x over previous
#include <cuda_runtime.h>
#include <math.h>

#define NCLS 40
#define QN 100
#define BN 4
#define HW 65536
#define THREADS 256
#define PPT 4
#define PIX (THREADS*PPT)          // 1024 pixels per block
#define NC1 (NCLS+1)
#define QG 4                       // q-groups
#define QPG (QN/QG)                // 25 queries per group
#define NPIX (BN*HW)               // 262144 pixels
#define PIXBLK (HW/PIX)            // 64 pixel-blocks per image
#define NBLK_MAIN (QG*BN*PIXBLK)   // 1024

// ---- scratch (device globals; no allocation allowed) ----
__device__ float g_inter[BN*QN*NCLS];
__device__ float g_src[BN*QN];
__device__ int   g_counts[BN*QN*NCLS];
__device__ float g_ce_sum;
__device__ int   g_nvalid;
// per-pixel per-group partials (~13.6 MB)
__device__ float4 g_pssum[QG][NPIX/4];
__device__ float4 g_pmax [QG][NPIX/4];
__device__ float4 g_pxt  [QG][NPIX/4];
__device__ uchar4 g_pamax[QG][NPIX/4];

__global__ void zero_k() {
    int i = blockIdx.x * blockDim.x + threadIdx.x;
    if (i < BN*QN*NCLS) { g_inter[i] = 0.f; g_counts[i] = 0; }
    if (i < BN*QN) g_src[i] = 0.f;
    if (i == 0) { g_ce_sum = 0.f; g_nvalid = 0; }
}

// Streaming pass: block = (q-group g, image, 1024 contiguous pixels).
// Loop over 25 q's, float4/thread, register prefetch. inter[q][c] via
// class-sorted shared staging. Per-pixel partials written for combine_k.
__global__ __launch_bounds__(THREADS) void main_k(
    const float* __restrict__ masks, const int* __restrict__ targets)
{
    // sig_sh is read with LDS.128 -> MUST be 16B aligned (round-4 bug:
    // inter_sh's 4100B pushed it to offset%16==4 -> misaligned address).
    __shared__ __align__(16) float sig_sh[2][PIX];  // double buffer: 1 barrier per q
    __shared__ float inter_sh[QPG*NC1];             // 4.1 KB, class 40 = ignore bin
    __shared__ unsigned char cls_sorted[PIX];
    __shared__ int s_cnt[NC1];
    __shared__ int s_base[NC1];
    __shared__ int s_cur[NC1];

    const int tid = threadIdx.x;
    const int g   = blockIdx.x / (BN*PIXBLK);
    const int rem = blockIdx.x % (BN*PIXBLK);
    const int img = rem / PIXBLK;
    const int blk = rem % PIXBLK;
    const int q0  = g*QPG;
    const int pixbase = img*HW + blk*PIX;

    for (int i = tid; i < QPG*NC1; i += THREADS) inter_sh[i] = 0.f;
    for (int i = tid; i < NC1; i += THREADS) s_cnt[i] = 0;
    __syncthreads();

    // ---- classes (4 contiguous pixels/thread) + counting sort by class ----
    int myc[PPT], mypos[PPT];
    {
        int4 t4 = reinterpret_cast<const int4*>(targets + pixbase)[tid];
        int tt[PPT] = {t4.x, t4.y, t4.z, t4.w};
        #pragma unroll
        for (int j = 0; j < PPT; j++) {
            myc[j] = ((unsigned)tt[j] < (unsigned)NCLS) ? tt[j] : NCLS; // 40 == ignore
            atomicAdd(&s_cnt[myc[j]], 1);
        }
    }
    __syncthreads();
    if (tid == 0) {
        int r = 0;
        for (int c = 0; c < NC1; c++) { s_base[c] = r; r += s_cnt[c]; }
    }
    __syncthreads();
    for (int i = tid; i < NC1; i += THREADS) s_cur[i] = s_base[i];
    __syncthreads();
    #pragma unroll
    for (int j = 0; j < PPT; j++) {
        mypos[j] = atomicAdd(&s_cur[myc[j]], 1);
        cls_sorted[mypos[j]] = (unsigned char)myc[j];
    }
    __syncthreads();
    int accCls[PPT];
    #pragma unroll
    for (int j = 0; j < PPT; j++) accCls[j] = (int)cls_sorted[tid*PPT + j];

    float ssum[PPT], mmax[PPT], xt[PPT];
    int amax[PPT];
    #pragma unroll
    for (int j = 0; j < PPT; j++) { ssum[j] = 0.f; mmax[j] = -1e30f; xt[j] = 0.f; amax[j] = q0; }

    const float4* base4 = reinterpret_cast<const float4*>(
        masks + (size_t)img*QN*HW + (size_t)blk*PIX);
    const int stride4 = HW/4;

    float4 cur = base4[(size_t)q0*stride4 + tid];      // prefetch first q
    for (int qi = 0; qi < QPG; qi++) {
        const int q = q0 + qi;
        // prefetch next q before any dependent work / barrier
        float4 nxt;
        if (qi + 1 < QPG) nxt = base4[(size_t)(q+1)*stride4 + tid];
        else nxt = make_float4(0.f, 0.f, 0.f, 0.f);

        float xv[PPT] = {cur.x, cur.y, cur.z, cur.w};
        float* sbuf = sig_sh[qi & 1];
        #pragma unroll
        for (int j = 0; j < PPT; j++) {
            float x = xv[j];
            if (x > mmax[j]) { mmax[j] = x; amax[j] = q; }
            xt[j] = (q == myc[j]) ? x : xt[j];
            float xc = fminf(fmaxf(x, -15.f), 15.f);
            float t = __expf(xc);              // one exp serves both lse and sigmoid
            ssum[j] += t;
            float sg = __fdividef(t, 1.f + t); // sigmoid
            sbuf[mypos[j]] = sg;               // scatter to class-sorted slot
        }
        __syncthreads();
        // accumulate: 4 consecutive class-sorted slots -> mostly one run
        float4 v = reinterpret_cast<const float4*>(sbuf)[tid];
        float* ip = &inter_sh[qi*NC1];
        float a = v.x; int c = accCls[0];
        if (accCls[1] == c) a += v.y; else { atomicAdd(ip + c, a); c = accCls[1]; a = v.y; }
        if (accCls[2] == c) a += v.z; else { atomicAdd(ip + c, a); c = accCls[2]; a = v.z; }
        if (accCls[3] == c) a += v.w; else { atomicAdd(ip + c, a); c = accCls[3]; a = v.w; }
        atomicAdd(ip + c, a);
        cur = nxt;
        // no 2nd barrier: next q writes the other buffer; its barrier orders reuse
    }

    // ---- write per-pixel partials for combine_k ----
    {
        const int p4 = pixbase/4 + tid;
        g_pssum[g][p4] = make_float4(ssum[0], ssum[1], ssum[2], ssum[3]);
        g_pmax [g][p4] = make_float4(mmax[0], mmax[1], mmax[2], mmax[3]);
        g_pxt  [g][p4] = make_float4(xt[0], xt[1], xt[2], xt[3]);
        g_pamax[g][p4] = make_uchar4((unsigned char)amax[0], (unsigned char)amax[1],
                                     (unsigned char)amax[2], (unsigned char)amax[3]);
    }
    __syncthreads();

    // ---- flush inter_sh -> global (src_sum = sum over all 41 bins incl. ignore) ----
    for (int qi = tid; qi < QPG; qi += THREADS) {
        float ss = 0.f;
        const int q = q0 + qi;
        #pragma unroll 1
        for (int c = 0; c < NC1; c++) {
            float v = inter_sh[qi*NC1 + c];
            ss += v;
            if (c < NCLS) atomicAdd(&g_inter[(img*QN + q)*NCLS + c], v);
        }
        atomicAdd(&g_src[img*QN + q], ss);
    }
}

// Cross-group combine: per-pixel ce_mask numerator, n_valid, assignment counts.
__global__ __launch_bounds__(THREADS) void combine_k(const int* __restrict__ targets)
{
    __shared__ float s_red[THREADS];
    const int tid = threadIdx.x;
    const int j = blockIdx.x * THREADS + tid;      // float4 pixel group

    float4 ssum = g_pssum[0][j];
    float4 mmax = g_pmax [0][j];
    float4 xt   = g_pxt  [0][j];
    uchar4 am   = g_pamax[0][j];
    #pragma unroll
    for (int g = 1; g < QG; g++) {
        float4 s2 = g_pssum[g][j];
        float4 m2 = g_pmax [g][j];
        float4 x2 = g_pxt  [g][j];
        uchar4 a2 = g_pamax[g][j];
        ssum.x += s2.x; ssum.y += s2.y; ssum.z += s2.z; ssum.w += s2.w;
        xt.x += x2.x; xt.y += x2.y; xt.z += x2.z; xt.w += x2.w;
        if (m2.x > mmax.x) { mmax.x = m2.x; am.x = a2.x; }
        if (m2.y > mmax.y) { mmax.y = m2.y; am.y = a2.y; }
        if (m2.z > mmax.z) { mmax.z = m2.z; am.z = a2.z; }
        if (m2.w > mmax.w) { mmax.w = m2.w; am.w = a2.w; }
    }
    int4 t4 = reinterpret_cast<const int4*>(targets)[j];
    const int img = (j*4) >> 16;                   // j*4 / HW

    float ce_l = 0.f, nv = 0.f;
    int tt[PPT] = {t4.x, t4.y, t4.z, t4.w};
    float ssv[PPT] = {ssum.x, ssum.y, ssum.z, ssum.w};
    float xtv[PPT] = {xt.x, xt.y, xt.z, xt.w};
    int amv[PPT] = {am.x, am.y, am.z, am.w};
    #pragma unroll
    for (int k = 0; k < PPT; k++) {
        if ((unsigned)tt[k] < (unsigned)NCLS) {
            ce_l += __logf(ssv[k]) - xtv[k];       // lse - x[target]
            nv += 1.f;
            atomicAdd(&g_counts[(img*QN + amv[k])*NCLS + tt[k]], 1);
        }
    }
    s_red[tid] = ce_l; __syncthreads();
    for (int s = THREADS/2; s > 0; s >>= 1) { if (tid < s) s_red[tid] += s_red[tid+s]; __syncthreads(); }
    if (tid == 0) atomicAdd(&g_ce_sum, s_red[0]);
    __syncthreads();
    s_red[tid] = nv; __syncthreads();
    for (int s = THREADS/2; s > 0; s >>= 1) { if (tid < s) s_red[tid] += s_red[tid+s]; __syncthreads(); }
    if (tid == 0) atomicAdd(&g_nvalid, (int)s_red[0]);
}

// Final reduction: loss_ce (focal CE over 400 queries), dice, combine.
__global__ void fin_k(const float* __restrict__ logits, float* __restrict__ out)
{
    __shared__ float tsum_sh[BN*NCLS];
    __shared__ float pres_sh[NCLS];
    __shared__ float red[512];
    const int tid = threadIdx.x;

    for (int idx = tid; idx < BN*NCLS; idx += 512) {
        int b = idx / NCLS, c = idx % NCLS;
        int s = 0;
        for (int q = 0; q < QN; q++) s += g_counts[(b*QN + q)*NCLS + c];
        tsum_sh[idx] = (float)s;
    }
    __syncthreads();
    for (int c = tid; c < NCLS; c += 512) {
        float t = 0.f;
        for (int b = 0; b < BN; b++) t += tsum_sh[b*NCLS + c];
        pres_sh[c] = (t > 0.f) ? 1.f : 0.f;
    }
    __syncthreads();

    float ce_acc = 0.f, dice_acc = 0.f;
    for (int i = tid; i < BN*QN; i += 512) {
        int b = i / QN;
        // mode label = argmax of counts (ties -> smallest class); empty -> NCLS
        const int* cp = &g_counts[i*NCLS];
        int bestc = NCLS, bestcnt = 0;
        for (int c = 0; c < NCLS; c++) { int v = cp[c]; if (v > bestcnt) { bestcnt = v; bestc = c; } }
        if (bestc < NCLS) {
            const float* lg = logits + i*NC1;
            float m = -1e30f;
            for (int c = 0; c < NC1; c++) m = fmaxf(m, lg[c]);
            float s = 0.f;
            for (int c = 0; c < NC1; c++) s += __expf(lg[c] - m);
            float nll = m + __logf(s) - lg[bestc];     // weight = 1 for c < NCLS
            float p = __expf(-nll);
            float om = 1.f - p;
            ce_acc += om * om * nll;
        }
        float ss = g_src[i];
        for (int c = 0; c < NCLS; c++) {
            dice_acc += pres_sh[c] * 2.f * g_inter[i*NCLS + c]
                        / (ss + tsum_sh[b*NCLS + c] + 1e-8f);
        }
    }

    red[tid] = ce_acc; __syncthreads();
    for (int s = 256; s > 0; s >>= 1) { if (tid < s) red[tid] += red[tid+s]; __syncthreads(); }
    float ce_tot = red[0]; __syncthreads();
    red[tid] = dice_acc; __syncthreads();
    for (int s = 256; s > 0; s >>= 1) { if (tid < s) red[tid] += red[tid+s]; __syncthreads(); }
    float dice_tot = red[0]; __syncthreads();

    if (tid == 0) {
        float npres = 0.f;
        for (int c = 0; c < NCLS; c++) npres += pres_sh[c];
        float loss_ce = ce_tot / (float)(BN*QN);
        float ce_mask = g_ce_sum / fmaxf((float)g_nvalid, 1.f);
        float dice_loss = (npres - dice_tot / (float)(BN*QN)) / (float)NCLS;
        out[0] = 2.f*loss_ce + 5.f*ce_mask + 5.f*dice_loss;
    }
}

extern "C" void kernel_launch(void* const* d_in, const int* in_sizes, int n_in,
                              void* d_out, int out_size)
{
    const float* logits  = (const float*)d_in[0];   // [4,100,41] f32
    const float* masks   = (const float*)d_in[1];   // [4,100,256,256] f32
    const int*   targets = (const int*)d_in[2];     // [4,256,256] i32
    float* out = (float*)d_out;

    zero_k<<<(BN*QN*NCLS + 255)/256, 256>>>();
    main_k<<<NBLK_MAIN, THREADS>>>(masks, targets);
    combine_k<<<NPIX/4/THREADS, THREADS>>>(targets);
    fin_k<<<1, 512>>>(logits, out);
}